// round 16
// baseline (speedup 1.0000x reference)
#include <cuda_runtime.h>
#include <cuda_fp16.h>
#include <math.h>
#include <stdint.h>

// Problem constants
#define Bn   2
#define Tn   2048
#define HIDn 2048
#define Hn   16
#define DKn  128
#define DVn  128
#define KCn  4
#define BTn  (Bn*Tn)      // 4096
#define CHn  (Hn*DKn)     // 2048

// ---------------- scratch (static device globals; no allocation) ----------------
__device__ float g_xq[BTn*CHn];
__device__ float g_xk[BTn*CHn];
__device__ float g_xv[BTn*CHn];
__device__ float g_q [BTn*CHn];
__device__ float g_k [BTn*CHn];
__device__ float g_v [BTn*CHn];
__device__ float g_gd[BTn*CHn];   // decay gate g (post-transform)
__device__ float g_g2[BTn*CHn];   // output gate pre-sigmoid
__device__ float g_o [BTn*CHn];   // recurrence output
__device__ float g_p1[4*BTn*DVn]; // split-K partials (fa)
__device__ float g_p2[4*BTn*DVn]; // split-K partials (ga)
__device__ float g_bt[BTn*Hn];    // beta (post-sigmoid)

// fp16 operand buffers
__device__ __half g_xh  [BTn*HIDn];
__device__ __half g_wqh [HIDn*CHn];
__device__ __half g_wkh [HIDn*CHn];
__device__ __half g_wvh [HIDn*CHn];
__device__ __half g_woh [CHn*HIDn];
__device__ __half g_wfah[HIDn*DVn];
__device__ __half g_wgah[HIDn*DVn];
__device__ __half g_wfbh[DVn*CHn];
__device__ __half g_wgbh[DVn*CHn];
__device__ __half g_t1h [BTn*DVn];
__device__ __half g_t2h [BTn*DVn];
__device__ __half g_oh  [BTn*CHn];

// pack two f32 -> f16x2 (lo, hi)
__device__ __forceinline__ uint32_t packh2(float lo, float hi) {
    uint32_t r;
    asm("cvt.rn.f16x2.f32 %0, %1, %2;" : "=r"(r) : "f"(hi), "f"(lo));
    return r;
}

// ---------------- f32 -> f16 conversion (streaming) ----------------
__global__ void f32_to_f16(const float* __restrict__ src, __half* __restrict__ dst, int n)
{
    int i = (blockIdx.x * blockDim.x + threadIdx.x) * 8;
    if (i >= n) return;
    float4 a = *(const float4*)(src + i);
    float4 b = *(const float4*)(src + i + 4);
    uint4 o;
    o.x = packh2(a.x, a.y); o.y = packh2(a.z, a.w);
    o.z = packh2(b.x, b.y); o.w = packh2(b.z, b.w);
    *(uint4*)(dst + i) = o;
}

// ---------------- FP16 GEMM v3: BK=32 per stage, 2-stage cp.async pipeline -----
// Block tile 128x128x32, 128 threads (4 warps, 64x64 warp tiles),
// ldmatrix + mma m16n8k16, one barrier per 32-K tile.
// smem per stage: A = 128 rows * 80B (64B data + 16B pad) = 10240B,
//                 B = 32 k-rows * 272B (256B data + 16B pad) = 8704B.
#define A_ST_B 10240
#define ST_B   18944

__device__ __forceinline__ void cp16cg(uint32_t dst, const void* src) {
    asm volatile("cp.async.cg.shared.global [%0], [%1], 16;" :: "r"(dst), "l"(src));
}

__device__ __forceinline__ float gate_xform(float acc, float dtbv, float ea) {
    float xv = acc + dtbv;
    float sp = (xv > 20.f) ? xv : log1pf(expf(xv));
    return expf(-sp * ea);
}

template<int GATE>
__device__ __forceinline__ void hgemm_body32(
    int M, int N, int K, int kbeg, int ntiles,
    const __half* __restrict__ A, const __half* __restrict__ B, float* __restrict__ C,
    const float* __restrict__ dtb, const float* __restrict__ A_log)
{
    __shared__ __align__(16) char sm[2][ST_B];

    const int tid  = threadIdx.x;
    const int lane = tid & 31;
    const int gid  = lane >> 2;
    const int tig  = lane & 3;
    const int warp = tid >> 5;           // 0..3
    const int warpM = (warp >> 1) * 64;  // 0 or 64
    const int warpN = (warp & 1) * 64;   // 0 or 64

    const int bx = blockIdx.x, by = blockIdx.y;

    const char* Abase = (const char*)A + ((size_t)(by * 128) * K + kbeg) * 2;
    const char* Bbase = (const char*)B + ((size_t)kbeg * N + bx * 128) * 2;

    const uint32_t smb = (uint32_t)__cvta_generic_to_shared(&sm[0][0]);

    // per-thread copy roles: 4 A-chunks + 4 B-chunks of 16B each
    int a_r[4], a_o[4], b_r[4], b_o[4];
    #pragma unroll
    for (int j = 0; j < 4; j++) {
        int ca = tid + 128 * j;
        a_r[j] = ca >> 2;  a_o[j] = (ca & 3) * 16;
        b_r[j] = ca >> 4;  b_o[j] = (ca & 15) * 16;
    }

    const uint32_t a_lm = smb + (warpM + (lane & 15)) * 80 + (lane >> 4) * 16;
    const uint32_t b_lm = smb + A_ST_B + (lane & 15) * 272 + warpN * 2;

    float acc[4][8][4];
    #pragma unroll
    for (int mt = 0; mt < 4; mt++)
        #pragma unroll
        for (int nt = 0; nt < 8; nt++)
            #pragma unroll
            for (int i = 0; i < 4; i++) acc[mt][nt][i] = 0.f;

    auto issue = [&](int t, int s) {
        const uint32_t so = (uint32_t)s * ST_B;
        #pragma unroll
        for (int j = 0; j < 4; j++) {
            cp16cg(smb + so + (uint32_t)(a_r[j] * 80 + a_o[j]),
                   Abase + (size_t)a_r[j] * K * 2 + (size_t)t * 64 + a_o[j]);
            cp16cg(smb + so + A_ST_B + (uint32_t)(b_r[j] * 272 + b_o[j]),
                   Bbase + (size_t)(t * 32 + b_r[j]) * N * 2 + b_o[j]);
        }
    };

    issue(0, 0);
    asm volatile("cp.async.commit_group;");

    for (int t = 0; t < ntiles; t++) {
        asm volatile("cp.async.wait_group 0;");
        __syncthreads();
        if (t + 1 < ntiles) {
            issue(t + 1, (t + 1) & 1);
            asm volatile("cp.async.commit_group;");
        }

        const uint32_t so = (uint32_t)(t & 1) * ST_B;
        #pragma unroll
        for (int kh = 0; kh < 2; kh++) {
            uint32_t bfr[8][2];
            #pragma unroll
            for (int nt = 0; nt < 8; nt++) {
                asm volatile("ldmatrix.sync.aligned.m8n8.x2.trans.shared.b16 {%0,%1}, [%2];"
                             : "=r"(bfr[nt][0]), "=r"(bfr[nt][1])
                             : "r"(b_lm + so + (uint32_t)(kh * 16 * 272 + nt * 16)));
            }
            #pragma unroll
            for (int mt = 0; mt < 4; mt++) {
                uint32_t afr[4];
                asm volatile("ldmatrix.sync.aligned.m8n8.x4.shared.b16 {%0,%1,%2,%3}, [%4];"
                             : "=r"(afr[0]), "=r"(afr[1]), "=r"(afr[2]), "=r"(afr[3])
                             : "r"(a_lm + so + (uint32_t)(kh * 32 + mt * 16 * 80)));
                #pragma unroll
                for (int nt = 0; nt < 8; nt++) {
                    asm volatile(
                        "mma.sync.aligned.m16n8k16.row.col.f32.f16.f16.f32 "
                        "{%0,%1,%2,%3}, {%4,%5,%6,%7}, {%8,%9}, {%0,%1,%2,%3};\n"
                        : "+f"(acc[mt][nt][0]), "+f"(acc[mt][nt][1]),
                          "+f"(acc[mt][nt][2]), "+f"(acc[mt][nt][3])
                        : "r"(afr[0]), "r"(afr[1]), "r"(afr[2]), "r"(afr[3]),
                          "r"(bfr[nt][0]), "r"(bfr[nt][1]));
                }
            }
        }
    }

    float ea = 0.f;
    if (GATE) ea = expf(A_log[bx]);   // gate use has N == CHn, head == bx

    #pragma unroll
    for (int mt = 0; mt < 4; mt++) {
        int r0 = by * 128 + warpM + mt * 16 + gid;
        #pragma unroll
        for (int nt = 0; nt < 8; nt++) {
            int c0 = bx * 128 + warpN + nt * 8 + tig * 2;
            float2 lo, hi;
            if (GATE) {
                float d0 = dtb[c0], d1 = dtb[c0 + 1];
                lo.x = gate_xform(acc[mt][nt][0], d0, ea);
                lo.y = gate_xform(acc[mt][nt][1], d1, ea);
                hi.x = gate_xform(acc[mt][nt][2], d0, ea);
                hi.y = gate_xform(acc[mt][nt][3], d1, ea);
            } else {
                lo.x = acc[mt][nt][0]; lo.y = acc[mt][nt][1];
                hi.x = acc[mt][nt][2]; hi.y = acc[mt][nt][3];
            }
            *(float2*)(C + (size_t)r0 * N + c0)       = lo;
            *(float2*)(C + (size_t)(r0 + 8) * N + c0) = hi;
        }
    }
}

__global__ __launch_bounds__(128) void hgemm(
    int M, int N, int K,
    const __half* __restrict__ A, const __half* __restrict__ B, float* __restrict__ C)
{
    hgemm_body32<0>(M, N, K, 0, K >> 5, A, B, C, nullptr, nullptr);
}

__global__ __launch_bounds__(128) void hgemm_gate(
    int M, int N, int K,
    const __half* __restrict__ A, const __half* __restrict__ B, float* __restrict__ C,
    const float* __restrict__ dtb, const float* __restrict__ A_log)
{
    hgemm_body32<1>(M, N, K, 0, K >> 5, A, B, C, dtb, A_log);
}

__global__ __launch_bounds__(128) void hgemm_splitk4(
    int M, int N, int K,
    const __half* __restrict__ A, const __half* __restrict__ B, float* __restrict__ Cpart)
{
    const int z = blockIdx.z;
    const int ks = K >> 2;
    hgemm_body32<0>(M, N, K, z * ks, ks >> 5, A, B, Cpart + (size_t)z * M * N, nullptr, nullptr);
}

// deterministic fixed-order reduction of 4 partial slabs -> fp16 output
__global__ void reduce4h(const float* __restrict__ p, __half* __restrict__ out, int n)
{
    int i = (blockIdx.x * blockDim.x + threadIdx.x) * 4;
    if (i >= n) return;
    float4 a = *(const float4*)(p + i);
    float4 b = *(const float4*)(p + (size_t)n + i);
    float4 c = *(const float4*)(p + 2 * (size_t)n + i);
    float4 d = *(const float4*)(p + 3 * (size_t)n + i);
    float rx = ((a.x + b.x) + c.x) + d.x;
    float ry = ((a.y + b.y) + c.y) + d.y;
    float rz = ((a.z + b.z) + c.z) + d.z;
    float rw = ((a.w + b.w) + c.w) + d.w;
    uint2 o;
    o.x = packh2(rx, ry);
    o.y = packh2(rz, rw);
    *(uint2*)(out + i) = o;
}

// ---------------- fused causal depthwise conv (KC=4) + silu for q,k,v ----------------
__global__ void conv_silu3(
    const float* __restrict__ xq, const float* __restrict__ xk, const float* __restrict__ xv,
    const float* __restrict__ wq, const float* __restrict__ wk, const float* __restrict__ wv,
    float* __restrict__ oq, float* __restrict__ ok, float* __restrict__ ov)
{
    int idx = blockIdx.x * blockDim.x + threadIdx.x;
    if (idx >= BTn * CHn) return;
    const float* x;
    const float* w;
    float* out;
    if (blockIdx.y == 0)      { x = xq; w = wq; out = oq; }
    else if (blockIdx.y == 1) { x = xk; w = wk; out = ok; }
    else                      { x = xv; w = wv; out = ov; }

    int c  = idx % CHn;
    int bt = idx / CHn;
    int t  = bt % Tn;
    int b  = bt / Tn;
    float s = 0.f;
    #pragma unroll
    for (int i = 0; i < KCn; i++) {
        int tt = t - (KCn - 1) + i;
        if (tt >= 0)
            s = fmaf(x[((size_t)(b * Tn + tt)) * CHn + c], w[c * KCn + i], s);
    }
    out[idx] = s * (1.f / (1.f + expf(-s)));
}

// ---------------- beta = sigmoid(x @ Wb) ----------------
__global__ __launch_bounds__(256) void beta_proj(
    const float* __restrict__ x, const float* __restrict__ Wb, float* __restrict__ beta)
{
    int warp = (blockIdx.x * blockDim.x + threadIdx.x) >> 5;
    int lane = threadIdx.x & 31;
    if (warp >= BTn) return;
    const float* xr = x + (size_t)warp * HIDn;
    float acc[Hn];
    #pragma unroll
    for (int n = 0; n < Hn; n++) acc[n] = 0.f;
    for (int k0 = lane; k0 < HIDn; k0 += 32) {
        float a = xr[k0];
        const float* br = Wb + (size_t)k0 * Hn;
        #pragma unroll
        for (int n = 0; n < Hn; n++) acc[n] = fmaf(a, br[n], acc[n]);
    }
    #pragma unroll
    for (int n = 0; n < Hn; n++) {
        #pragma unroll
        for (int o = 16; o; o >>= 1) acc[n] += __shfl_xor_sync(0xffffffffu, acc[n], o);
    }
    if (lane == 0) {
        #pragma unroll
        for (int n = 0; n < Hn; n++)
            beta[warp * Hn + n] = 1.f / (1.f + expf(-acc[n]));
    }
}

// ---------------- in-place L2 norm of q (scaled) and k ----------------
__global__ __launch_bounds__(256) void l2norm_qk(float* __restrict__ q, float* __restrict__ k)
{
    int warp = (blockIdx.x * blockDim.x + threadIdx.x) >> 5;
    int lane = threadIdx.x & 31;
    if (warp >= BTn * Hn) return;

    float4* qp = (float4*)(q + (size_t)warp * DKn);
    float4 v = qp[lane];
    float ss = v.x*v.x + v.y*v.y + v.z*v.z + v.w*v.w;
    #pragma unroll
    for (int o = 16; o; o >>= 1) ss += __shfl_xor_sync(0xffffffffu, ss, o);
    float r = rsqrtf(ss + 1e-6f) * 0.08838834764831845f;
    v.x *= r; v.y *= r; v.z *= r; v.w *= r;
    qp[lane] = v;

    float4* kp = (float4*)(k + (size_t)warp * DKn);
    float4 u = kp[lane];
    float sk = u.x*u.x + u.y*u.y + u.z*u.z + u.w*u.w;
    #pragma unroll
    for (int o = 16; o; o >>= 1) sk += __shfl_xor_sync(0xffffffffu, sk, o);
    float rk = rsqrtf(sk + 1e-6f);
    u.x *= rk; u.y *= rk; u.z *= rk; u.w *= rk;
    kp[lane] = u;
}

// ---------------- cp.async helpers (recurrence) ----------------
__device__ __forceinline__ void cp16(uint32_t dst, const void* src) {
    asm volatile("cp.async.ca.shared.global [%0], [%1], 16;" :: "r"(dst), "l"(src));
}
__device__ __forceinline__ void cp4(uint32_t dst, const void* src) {
    asm volatile("cp.async.ca.shared.global [%0], [%1], 4;" :: "r"(dst), "l"(src));
}

// ---------------- gated delta-rule recurrence (v5: barrier-free, 4-deep pipe) ---
__global__ __launch_bounds__(128) void recurrence(
    const float* __restrict__ q, const float* __restrict__ k, const float* __restrict__ v,
    const float* __restrict__ g, const float* __restrict__ beta, float* __restrict__ o)
{
    const int bh = blockIdx.x;
    const int b = bh >> 4, h = bh & 15;
    const int jbase = (blockIdx.y << 5);
    const int tid = threadIdx.x;
    const int w    = tid >> 5;
    const int lane = tid & 31;
    const int r4   = lane >> 3;
    const int c    = lane & 7;

    __shared__ __align__(16) float sw[4][4][400];   // [warp][buf][data]

    unsigned long long S2[16];
    #pragma unroll
    for (int i = 0; i < 16; i++) S2[i] = 0ull;

    const size_t rs = (size_t)CHn;
    const size_t base0 = ((size_t)b * Tn) * rs + (size_t)h * DKn;
    const int jcol = jbase + w * 8;
    const size_t bbase = (size_t)(b * Tn) * Hn + h;

    float* swarp = &sw[w][0][0];
    const uint32_t sb32 = (uint32_t)__cvta_generic_to_shared(swarp);

    auto issue_copy = [&](int t, int bb) {
        const uint32_t d = sb32 + (uint32_t)bb * 400u * 4u;
        const size_t row = base0 + (size_t)t * rs;
        cp16(d +            lane * 16, k + row + lane * 4);
        cp16(d + 128 * 4 +  lane * 16, g + row + lane * 4);
        cp16(d + 256 * 4 +  lane * 16, q + row + lane * 4);
        if (lane < 2)  cp16(d + 384 * 4 + lane * 16, v + row + jcol + lane * 4);
        if (lane == 2) cp4 (d + 392 * 4, beta + bbase + (size_t)t * Hn);
    };

    issue_copy(0, 0);
    asm volatile("cp.async.commit_group;");
    issue_copy(1, 1);
    asm volatile("cp.async.commit_group;");
    issue_copy(2, 2);
    asm volatile("cp.async.commit_group;");

    size_t obase = base0 + jcol + c;

    #pragma unroll 1
    for (int t = 0; t < Tn; t++) {
        const int bb = t & 3;
        if (t + 3 < Tn) issue_copy(t + 3, (t + 3) & 3);
        asm volatile("cp.async.commit_group;");
        asm volatile("cp.async.wait_group 3;");
        __syncwarp();

        const float* buf = &sw[w][bb][0];
        const ulonglong2* kp = (const ulonglong2*)(buf +       r4 * 32);
        const ulonglong2* gp = (const ulonglong2*)(buf + 128 + r4 * 32);
        const ulonglong2* qp = (const ulonglong2*)(buf + 256 + r4 * 32);

        unsigned long long k2[16];
        unsigned long long p[4] = {0ull, 0ull, 0ull, 0ull};
        #pragma unroll
        for (int i = 0; i < 8; i++) {
            ulonglong2 kv = kp[i];
            ulonglong2 gv = gp[i];
            k2[2*i]   = kv.x;
            k2[2*i+1] = kv.y;
            asm("mul.rn.f32x2 %0, %0, %1;" : "+l"(S2[2*i])   : "l"(gv.x));
            asm("mul.rn.f32x2 %0, %0, %1;" : "+l"(S2[2*i+1]) : "l"(gv.y));
        }
        #pragma unroll
        for (int i = 0; i < 16; i++)
            asm("fma.rn.f32x2 %0, %1, %2, %0;" : "+l"(p[i & 3]) : "l"(k2[i]), "l"(S2[i]));

        float partial;
        {
            unsigned long long p01, p23, pt;
            asm("add.rn.f32x2 %0, %1, %2;" : "=l"(p01) : "l"(p[0]), "l"(p[1]));
            asm("add.rn.f32x2 %0, %1, %2;" : "=l"(p23) : "l"(p[2]), "l"(p[3]));
            asm("add.rn.f32x2 %0, %1, %2;" : "=l"(pt)  : "l"(p01),  "l"(p23));
            unsigned int lo, hi;
            asm("mov.b64 {%0,%1}, %2;" : "=r"(lo), "=r"(hi) : "l"(pt));
            partial = __uint_as_float(lo) + __uint_as_float(hi);
        }
        partial += __shfl_xor_sync(0xffffffffu, partial, 8);
        partial += __shfl_xor_sync(0xffffffffu, partial, 16);

        const float vv = buf[384 + c];
        const float bt_ = buf[392];
        const float delta = (vv - partial) * bt_;
        unsigned long long d2;
        asm("mov.b64 %0, {%1,%1};" : "=l"(d2) : "r"(__float_as_uint(delta)));

        unsigned long long oacc[4] = {0ull, 0ull, 0ull, 0ull};
        #pragma unroll
        for (int i = 0; i < 8; i++) {
            ulonglong2 qv = qp[i];
            asm("fma.rn.f32x2 %0, %1, %2, %0;" : "+l"(S2[2*i])   : "l"(k2[2*i]),   "l"(d2));
            asm("fma.rn.f32x2 %0, %1, %2, %0;" : "+l"(S2[2*i+1]) : "l"(k2[2*i+1]), "l"(d2));
            asm("fma.rn.f32x2 %0, %1, %2, %0;" : "+l"(oacc[(2*i) & 3])   : "l"(qv.x), "l"(S2[2*i]));
            asm("fma.rn.f32x2 %0, %1, %2, %0;" : "+l"(oacc[(2*i+1) & 3]) : "l"(qv.y), "l"(S2[2*i+1]));
        }
        float oo;
        {
            unsigned long long o01, o23, ot;
            asm("add.rn.f32x2 %0, %1, %2;" : "=l"(o01) : "l"(oacc[0]), "l"(oacc[1]));
            asm("add.rn.f32x2 %0, %1, %2;" : "=l"(o23) : "l"(oacc[2]), "l"(oacc[3]));
            asm("add.rn.f32x2 %0, %1, %2;" : "=l"(ot)  : "l"(o01),     "l"(o23));
            unsigned int lo, hi;
            asm("mov.b64 {%0,%1}, %2;" : "=r"(lo), "=r"(hi) : "l"(ot));
            oo = __uint_as_float(lo) + __uint_as_float(hi);
        }
        oo += __shfl_xor_sync(0xffffffffu, oo, 8);
        oo += __shfl_xor_sync(0xffffffffu, oo, 16);

        if (r4 == 0) o[obase] = oo;
        obase += rs;
    }
}

// ---------------- gated RMSNorm -> fp16 output ----------------
__global__ __launch_bounds__(256) void rms_gate_h(
    const float* __restrict__ o, const float* __restrict__ g2,
    const float* __restrict__ nw, __half* __restrict__ oh)
{
    int warp = (blockIdx.x * blockDim.x + threadIdx.x) >> 5;
    int lane = threadIdx.x & 31;
    if (warp >= BTn * Hn) return;

    const float4* op = (const float4*)(o + (size_t)warp * DVn);
    const float4* gp = (const float4*)(g2 + (size_t)warp * DVn);
    const float4* wp = (const float4*)nw;

    float4 v = op[lane];
    float ss = v.x*v.x + v.y*v.y + v.z*v.z + v.w*v.w;
    #pragma unroll
    for (int off = 16; off; off >>= 1) ss += __shfl_xor_sync(0xffffffffu, ss, off);
    float r = rsqrtf(ss * (1.f / 128.f) + 1e-6f);

    float4 w = wp[lane];
    float4 gg = gp[lane];
    float ox = v.x * r * w.x * (1.f / (1.f + expf(-gg.x)));
    float oy = v.y * r * w.y * (1.f / (1.f + expf(-gg.y)));
    float oz = v.z * r * w.z * (1.f / (1.f + expf(-gg.z)));
    float ow = v.w * r * w.w * (1.f / (1.f + expf(-gg.w)));
    uint2 pk;
    pk.x = packh2(ox, oy);
    pk.y = packh2(oz, ow);
    *(uint2*)(oh + (size_t)warp * DVn + lane * 4) = pk;
}

// ---------------- launcher ----------------
extern "C" void kernel_launch(void* const* d_in, const int* in_sizes, int n_in,
                              void* d_out, int out_size)
{
    const float* x     = (const float*)d_in[0];
    const float* Wq    = (const float*)d_in[1];
    const float* Wk    = (const float*)d_in[2];
    const float* Wv    = (const float*)d_in[3];
    const float* convq = (const float*)d_in[4];
    const float* convk = (const float*)d_in[5];
    const float* convv = (const float*)d_in[6];
    const float* A_log = (const float*)d_in[7];
    const float* Wfa   = (const float*)d_in[8];
    const float* Wfb   = (const float*)d_in[9];
    const float* dtb   = (const float*)d_in[10];
    const float* Wb    = (const float*)d_in[11];
    const float* Wga   = (const float*)d_in[12];
    const float* Wgb   = (const float*)d_in[13];
    const float* nw    = (const float*)d_in[14];
    const float* Wo    = (const float*)d_in[15];

    float *xq, *xk, *xv, *q, *k, *v, *gd, *g2b, *ob, *p1, *p2, *bt;
    __half *xh, *wqh, *wkh, *wvh, *woh, *wfah, *wgah, *wfbh, *wgbh, *t1h, *t2h, *oh;
    cudaGetSymbolAddress((void**)&xq,  g_xq);
    cudaGetSymbolAddress((void**)&xk,  g_xk);
    cudaGetSymbolAddress((void**)&xv,  g_xv);
    cudaGetSymbolAddress((void**)&q,   g_q);
    cudaGetSymbolAddress((void**)&k,   g_k);
    cudaGetSymbolAddress((void**)&v,   g_v);
    cudaGetSymbolAddress((void**)&gd,  g_gd);
    cudaGetSymbolAddress((void**)&g2b, g_g2);
    cudaGetSymbolAddress((void**)&ob,  g_o);
    cudaGetSymbolAddress((void**)&p1,  g_p1);
    cudaGetSymbolAddress((void**)&p2,  g_p2);
    cudaGetSymbolAddress((void**)&bt,  g_bt);
    cudaGetSymbolAddress((void**)&xh,   g_xh);
    cudaGetSymbolAddress((void**)&wqh,  g_wqh);
    cudaGetSymbolAddress((void**)&wkh,  g_wkh);
    cudaGetSymbolAddress((void**)&wvh,  g_wvh);
    cudaGetSymbolAddress((void**)&woh,  g_woh);
    cudaGetSymbolAddress((void**)&wfah, g_wfah);
    cudaGetSymbolAddress((void**)&wgah, g_wgah);
    cudaGetSymbolAddress((void**)&wfbh, g_wfbh);
    cudaGetSymbolAddress((void**)&wgbh, g_wgbh);
    cudaGetSymbolAddress((void**)&t1h,  g_t1h);
    cudaGetSymbolAddress((void**)&t2h,  g_t2h);
    cudaGetSymbolAddress((void**)&oh,   g_oh);

    dim3 gBig(CHn / 128, BTn / 128);          // (16, 32)
    dim3 gNarrowSK(1, BTn / 128, 4);          // (1, 32, 4)
    int  tot = BTn * CHn;
    int  eb  = (tot + 255) / 256;
    int  nsm = BTn * DVn;

    auto cvtGrid = [](int n) { return (n / 8 + 255) / 256; };
    const int nBig = HIDn * CHn;
    const int nNar = HIDn * DVn;

    // idx 0-2: conversions needed by the first big GEMM
    f32_to_f16<<<cvtGrid(BTn * HIDn), 256>>>(x, xh, BTn * HIDn);
    f32_to_f16<<<cvtGrid(nBig), 256>>>(Wq, wqh, nBig);
    f32_to_f16<<<cvtGrid(nBig), 256>>>(Wk, wkh, nBig);

    // idx 3: first big projection  <-- ncu capture target (launch index 3)
    hgemm<<<gBig, 128>>>(BTn, CHn, HIDn, xh, wqh, xq);

    // idx 4: Wv conversion, idx 5-6: remaining big projections
    f32_to_f16<<<cvtGrid(nBig), 256>>>(Wv, wvh, nBig);
    hgemm<<<gBig, 128>>>(BTn, CHn, HIDn, xh, wkh, xk);
    hgemm<<<gBig, 128>>>(BTn, CHn, HIDn, xh, wvh, xv);

    // idx 7-11: remaining weight conversions
    f32_to_f16<<<cvtGrid(nBig), 256>>>(Wo, woh, nBig);
    f32_to_f16<<<cvtGrid(nNar), 256>>>(Wfa, wfah, nNar);
    f32_to_f16<<<cvtGrid(nNar), 256>>>(Wga, wgah, nNar);
    f32_to_f16<<<cvtGrid(nNar), 256>>>(Wfb, wfbh, nNar);
    f32_to_f16<<<cvtGrid(nNar), 256>>>(Wgb, wgbh, nNar);

    // idx 12: beta
    beta_proj<<<(BTn * 32 + 255) / 256, 256>>>(x, Wb, bt);

    // idx 13-14: narrow split-K GEMMs
    hgemm_splitk4<<<gNarrowSK, 128>>>(BTn, DVn, HIDn, xh, wfah, p1);
    hgemm_splitk4<<<gNarrowSK, 128>>>(BTn, DVn, HIDn, xh, wgah, p2);

    // idx 15-16: split-K reductions -> fp16
    reduce4h<<<(nsm / 4 + 255) / 256, 256>>>(p1, t1h, nsm);
    reduce4h<<<(nsm / 4 + 255) / 256, 256>>>(p2, t2h, nsm);

    // idx 17: fused conv+silu
    conv_silu3<<<dim3(eb, 3), 256>>>(xq, xk, xv, convq, convk, convv, q, k, v);

    // idx 18: decay gate GEMM with fused softplus/exp epilogue
    hgemm_gate<<<gBig, 128>>>(BTn, CHn, DVn, t1h, wfbh, gd, dtb, A_log);

    // idx 19: output gate GEMM
    hgemm<<<gBig, 128>>>(BTn, CHn, DVn, t2h, wgbh, g2b);

    // idx 20: L2 normalize
    l2norm_qk<<<(BTn * Hn) / 8, 256>>>(q, k);

    // idx 21: recurrence (v5)
    recurrence<<<dim3(Bn * Hn, 4), 128>>>(q, k, v, gd, bt, ob);

    // idx 22: gated RMSNorm -> fp16
    rms_gate_h<<<(BTn * Hn) / 8, 256>>>(ob, g2b, nw, oh);

    // idx 23: output projection
    hgemm<<<gBig, 128>>>(BTn, CHn, CHn, oh, woh, (float*)d_out);
}

// round 17
// speedup vs baseline: 1.0216x; 1.0216x over previous
#include <cuda_runtime.h>
#include <cuda_fp16.h>
#include <math.h>
#include <stdint.h>

// Problem constants
#define Bn   2
#define Tn   2048
#define HIDn 2048
#define Hn   16
#define DKn  128
#define DVn  128
#define KCn  4
#define BTn  (Bn*Tn)      // 4096
#define CHn  (Hn*DKn)     // 2048

// ---------------- scratch (static device globals; no allocation) ----------------
__device__ float g_xq[BTn*CHn];
__device__ float g_xk[BTn*CHn];
__device__ float g_xv[BTn*CHn];
__device__ float g_q [BTn*CHn];
__device__ float g_k [BTn*CHn];
__device__ float g_v [BTn*CHn];
__device__ float g_gd[BTn*CHn];   // decay gate g (post-transform)
__device__ float g_g2[BTn*CHn];   // output gate pre-sigmoid
__device__ float g_o [BTn*CHn];   // recurrence output
__device__ float g_p1[4*BTn*DVn]; // split-K partials (fa)
__device__ float g_p2[4*BTn*DVn]; // split-K partials (ga)
__device__ float g_bt[BTn*Hn];    // beta (post-sigmoid)

// fp16 operand buffers
__device__ __half g_xh  [BTn*HIDn];
__device__ __half g_wqh [HIDn*CHn];
__device__ __half g_wkh [HIDn*CHn];
__device__ __half g_wvh [HIDn*CHn];
__device__ __half g_woh [CHn*HIDn];
__device__ __half g_wfah[HIDn*DVn];
__device__ __half g_wgah[HIDn*DVn];
__device__ __half g_wfbh[DVn*CHn];
__device__ __half g_wgbh[DVn*CHn];
__device__ __half g_t1h [BTn*DVn];
__device__ __half g_t2h [BTn*DVn];
__device__ __half g_oh  [BTn*CHn];

// pack two f32 -> f16x2 (lo, hi)
__device__ __forceinline__ uint32_t packh2(float lo, float hi) {
    uint32_t r;
    asm("cvt.rn.f16x2.f32 %0, %1, %2;" : "=r"(r) : "f"(hi), "f"(lo));
    return r;
}

// ---------------- f32 -> f16 conversion (streaming) ----------------
__global__ void f32_to_f16(const float* __restrict__ src, __half* __restrict__ dst, int n)
{
    int i = (blockIdx.x * blockDim.x + threadIdx.x) * 8;
    if (i >= n) return;
    float4 a = *(const float4*)(src + i);
    float4 b = *(const float4*)(src + i + 4);
    uint4 o;
    o.x = packh2(a.x, a.y); o.y = packh2(a.z, a.w);
    o.z = packh2(b.x, b.y); o.w = packh2(b.z, b.w);
    *(uint4*)(dst + i) = o;
}

// ---------------- FP16 GEMM (R15-proven): BK=16, 3-stage cp.async pipeline -----
// Block tile 128x128x16, 128 threads (4 warps, 64x64 warp tiles),
// ldmatrix + mma m16n8k16. Optional fused decay-gate epilogue (GATE=1).
#define A32   1536            // A b32 per stage
#define B32   1088            // B b32 per stage
#define ST32  (A32 + B32)     // 2624 b32 = 10496 bytes
#define STB   (ST32 * 4)

__device__ __forceinline__ void cp16cg(uint32_t dst, const void* src) {
    asm volatile("cp.async.cg.shared.global [%0], [%1], 16;" :: "r"(dst), "l"(src));
}

__device__ __forceinline__ float gate_xform(float acc, float dtbv, float ea) {
    float xv = acc + dtbv;
    float sp = (xv > 20.f) ? xv : log1pf(expf(xv));
    return expf(-sp * ea);
}

template<int GATE>
__device__ __forceinline__ void hgemm_body(
    int M, int N, int K, int kbeg, int ntiles,
    const __half* __restrict__ A, const __half* __restrict__ B, float* __restrict__ C,
    const float* __restrict__ dtb, const float* __restrict__ A_log)
{
    __shared__ __align__(16) uint32_t sm[3][ST32];

    const int tid  = threadIdx.x;
    const int lane = tid & 31;
    const int gid  = lane >> 2;
    const int tig  = lane & 3;
    const int warp = tid >> 5;           // 0..3
    const int warpM = (warp >> 1) * 64;  // 0 or 64
    const int warpN = (warp & 1) * 64;   // 0 or 64

    const int bx = blockIdx.x, by = blockIdx.y;

    const int arow0 = tid >> 1,        ah0 = tid & 1;
    const int arow1 = (tid >> 1) + 64, ah1 = tid & 1;
    const int brow0 = tid >> 4,        bc0 = tid & 15;
    const int brow1 = (tid >> 4) + 8,  bc1 = tid & 15;

    const char* aS0 = (const char*)(A + (size_t)(by * 128 + arow0) * K + kbeg) + ah0 * 16;
    const char* aS1 = (const char*)(A + (size_t)(by * 128 + arow1) * K + kbeg) + ah1 * 16;
    const char* bS0 = (const char*)(B + (size_t)(kbeg + brow0) * N + bx * 128 + bc0 * 8);
    const char* bS1 = (const char*)(B + (size_t)(kbeg + brow1) * N + bx * 128 + bc1 * 8);
    const size_t bAdv = (size_t)16 * N * 2;

    const uint32_t smb = (uint32_t)__cvta_generic_to_shared(&sm[0][0]);
    const uint32_t aD0 = smb + arow0 * 48 + ah0 * 16;
    const uint32_t aD1 = smb + arow1 * 48 + ah1 * 16;
    const uint32_t bD0 = smb + A32 * 4 + brow0 * 272 + bc0 * 16;
    const uint32_t bD1 = smb + A32 * 4 + brow1 * 272 + bc1 * 16;

    const uint32_t a_lm = smb + (warpM + (lane & 15)) * 48 + (lane >> 4) * 16;
    const uint32_t b_lm = smb + A32 * 4 + (lane & 15) * 272 + warpN * 2;

    float acc[4][8][4];
    #pragma unroll
    for (int mt = 0; mt < 4; mt++)
        #pragma unroll
        for (int nt = 0; nt < 8; nt++)
            #pragma unroll
            for (int i = 0; i < 4; i++) acc[mt][nt][i] = 0.f;

    auto issue = [&](int t, int s) {
        uint32_t so = (uint32_t)s * STB;
        size_t ka = (size_t)t * 32;
        cp16cg(aD0 + so, aS0 + ka);
        cp16cg(aD1 + so, aS1 + ka);
        size_t kb = (size_t)t * bAdv;
        cp16cg(bD0 + so, bS0 + kb);
        cp16cg(bD1 + so, bS1 + kb);
    };

    issue(0, 0);
    asm volatile("cp.async.commit_group;");
    if (ntiles > 1) issue(1, 1);
    asm volatile("cp.async.commit_group;");

    for (int t = 0; t < ntiles; t++) {
        asm volatile("cp.async.wait_group 1;");
        __syncthreads();
        if (t + 2 < ntiles) issue(t + 2, (t + 2) % 3);
        asm volatile("cp.async.commit_group;");

        const uint32_t so = (uint32_t)(t % 3) * STB;
        uint32_t bfr[8][2];
        #pragma unroll
        for (int nt = 0; nt < 8; nt++) {
            asm volatile("ldmatrix.sync.aligned.m8n8.x2.trans.shared.b16 {%0,%1}, [%2];"
                         : "=r"(bfr[nt][0]), "=r"(bfr[nt][1])
                         : "r"(b_lm + so + (uint32_t)(nt * 16)));
        }
        #pragma unroll
        for (int mt = 0; mt < 4; mt++) {
            uint32_t afr[4];
            asm volatile("ldmatrix.sync.aligned.m8n8.x4.shared.b16 {%0,%1,%2,%3}, [%4];"
                         : "=r"(afr[0]), "=r"(afr[1]), "=r"(afr[2]), "=r"(afr[3])
                         : "r"(a_lm + so + (uint32_t)(mt * 16 * 48)));
            #pragma unroll
            for (int nt = 0; nt < 8; nt++) {
                asm volatile(
                    "mma.sync.aligned.m16n8k16.row.col.f32.f16.f16.f32 "
                    "{%0,%1,%2,%3}, {%4,%5,%6,%7}, {%8,%9}, {%0,%1,%2,%3};\n"
                    : "+f"(acc[mt][nt][0]), "+f"(acc[mt][nt][1]),
                      "+f"(acc[mt][nt][2]), "+f"(acc[mt][nt][3])
                    : "r"(afr[0]), "r"(afr[1]), "r"(afr[2]), "r"(afr[3]),
                      "r"(bfr[nt][0]), "r"(bfr[nt][1]));
            }
        }
    }

    float ea = 0.f;
    if (GATE) ea = expf(A_log[bx]);   // gate use: N == CHn, head == bx

    #pragma unroll
    for (int mt = 0; mt < 4; mt++) {
        int r0 = by * 128 + warpM + mt * 16 + gid;
        #pragma unroll
        for (int nt = 0; nt < 8; nt++) {
            int c0 = bx * 128 + warpN + nt * 8 + tig * 2;
            float2 lo, hi;
            if (GATE) {
                float d0 = dtb[c0], d1 = dtb[c0 + 1];
                lo.x = gate_xform(acc[mt][nt][0], d0, ea);
                lo.y = gate_xform(acc[mt][nt][1], d1, ea);
                hi.x = gate_xform(acc[mt][nt][2], d0, ea);
                hi.y = gate_xform(acc[mt][nt][3], d1, ea);
            } else {
                lo.x = acc[mt][nt][0]; lo.y = acc[mt][nt][1];
                hi.x = acc[mt][nt][2]; hi.y = acc[mt][nt][3];
            }
            *(float2*)(C + (size_t)r0 * N + c0)       = lo;
            *(float2*)(C + (size_t)(r0 + 8) * N + c0) = hi;
        }
    }
}

__global__ __launch_bounds__(128) void hgemm(
    int M, int N, int K,
    const __half* __restrict__ A, const __half* __restrict__ B, float* __restrict__ C)
{
    hgemm_body<0>(M, N, K, 0, K >> 4, A, B, C, nullptr, nullptr);
}

__global__ __launch_bounds__(128) void hgemm_gate(
    int M, int N, int K,
    const __half* __restrict__ A, const __half* __restrict__ B, float* __restrict__ C,
    const float* __restrict__ dtb, const float* __restrict__ A_log)
{
    hgemm_body<1>(M, N, K, 0, K >> 4, A, B, C, dtb, A_log);
}

__global__ __launch_bounds__(128) void hgemm_splitk4(
    int M, int N, int K,
    const __half* __restrict__ A, const __half* __restrict__ B, float* __restrict__ Cpart)
{
    const int z = blockIdx.z;
    const int ks = K >> 2;
    hgemm_body<0>(M, N, K, z * ks, ks >> 4, A, B, Cpart + (size_t)z * M * N, nullptr, nullptr);
}

// deterministic fixed-order reduction of 4 partial slabs -> fp16 output
__global__ void reduce4h(const float* __restrict__ p, __half* __restrict__ out, int n)
{
    int i = (blockIdx.x * blockDim.x + threadIdx.x) * 4;
    if (i >= n) return;
    float4 a = *(const float4*)(p + i);
    float4 b = *(const float4*)(p + (size_t)n + i);
    float4 c = *(const float4*)(p + 2 * (size_t)n + i);
    float4 d = *(const float4*)(p + 3 * (size_t)n + i);
    float rx = ((a.x + b.x) + c.x) + d.x;
    float ry = ((a.y + b.y) + c.y) + d.y;
    float rz = ((a.z + b.z) + c.z) + d.z;
    float rw = ((a.w + b.w) + c.w) + d.w;
    uint2 o;
    o.x = packh2(rx, ry);
    o.y = packh2(rz, rw);
    *(uint2*)(out + i) = o;
}

// ---------------- conv+silu (elementwise) for v ----------------
__global__ void conv_silu_v(const float* __restrict__ x, const float* __restrict__ w,
                            float* __restrict__ out)
{
    int idx = blockIdx.x * blockDim.x + threadIdx.x;
    if (idx >= BTn * CHn) return;
    int c  = idx % CHn;
    int bt = idx / CHn;
    int t  = bt % Tn;
    int b  = bt / Tn;
    float s = 0.f;
    #pragma unroll
    for (int i = 0; i < KCn; i++) {
        int tt = t - (KCn - 1) + i;
        if (tt >= 0)
            s = fmaf(x[((size_t)(b * Tn + tt)) * CHn + c], w[c * KCn + i], s);
    }
    out[idx] = s * (1.f / (1.f + expf(-s)));
}

// ---------------- fused conv + silu + L2-norm for q,k ----------------
// warp per (bt, h) row; lane holds 4 consecutive channels. blockIdx.y: 0=q, 1=k.
__global__ __launch_bounds__(256) void conv_silu_l2(
    const float* __restrict__ xq, const float* __restrict__ xk,
    const float* __restrict__ wq, const float* __restrict__ wk,
    float* __restrict__ oq, float* __restrict__ ok)
{
    int gw   = (blockIdx.x * blockDim.x + threadIdx.x) >> 5;  // row index
    int lane = threadIdx.x & 31;
    if (gw >= BTn * Hn) return;

    const float* x; const float* w; float* out; float scale;
    if (blockIdx.y == 0) { x = xq; w = wq; out = oq; scale = 0.08838834764831845f; }
    else                 { x = xk; w = wk; out = ok; scale = 1.f; }

    int bt = gw >> 4;          // 0..BTn-1
    int h  = gw & 15;
    int t  = bt % Tn;
    int b  = bt / Tn;
    int c0 = h * DKn + lane * 4;

    // weights: w[(c0..c0+3)][0..3] contiguous = 4 float4
    const float4* wv = (const float4*)(w + (size_t)c0 * KCn);
    float4 w0 = wv[0], w1 = wv[1], w2 = wv[2], w3 = wv[3];

    float4 acc = make_float4(0.f, 0.f, 0.f, 0.f);
    #pragma unroll
    for (int i = 0; i < KCn; i++) {
        int tt = t - (KCn - 1) + i;
        if (tt >= 0) {
            float4 xv = *(const float4*)(x + ((size_t)(b * Tn + tt)) * CHn + c0);
            acc.x = fmaf(xv.x, ((const float*)&w0)[i], acc.x);
            acc.y = fmaf(xv.y, ((const float*)&w1)[i], acc.y);
            acc.z = fmaf(xv.z, ((const float*)&w2)[i], acc.z);
            acc.w = fmaf(xv.w, ((const float*)&w3)[i], acc.w);
        }
    }
    // silu
    acc.x = acc.x * (1.f / (1.f + expf(-acc.x)));
    acc.y = acc.y * (1.f / (1.f + expf(-acc.y)));
    acc.z = acc.z * (1.f / (1.f + expf(-acc.z)));
    acc.w = acc.w * (1.f / (1.f + expf(-acc.w)));

    // L2 norm across the 128-channel row
    float ss = acc.x*acc.x + acc.y*acc.y + acc.z*acc.z + acc.w*acc.w;
    #pragma unroll
    for (int o = 16; o; o >>= 1) ss += __shfl_xor_sync(0xffffffffu, ss, o);
    float r = rsqrtf(ss + 1e-6f) * scale;
    acc.x *= r; acc.y *= r; acc.z *= r; acc.w *= r;

    *(float4*)(out + (size_t)bt * CHn + c0) = acc;
}

// ---------------- beta = sigmoid(x @ Wb) ----------------
__global__ __launch_bounds__(256) void beta_proj(
    const float* __restrict__ x, const float* __restrict__ Wb, float* __restrict__ beta)
{
    int warp = (blockIdx.x * blockDim.x + threadIdx.x) >> 5;
    int lane = threadIdx.x & 31;
    if (warp >= BTn) return;
    const float* xr = x + (size_t)warp * HIDn;
    float acc[Hn];
    #pragma unroll
    for (int n = 0; n < Hn; n++) acc[n] = 0.f;
    for (int k0 = lane; k0 < HIDn; k0 += 32) {
        float a = xr[k0];
        const float* br = Wb + (size_t)k0 * Hn;
        #pragma unroll
        for (int n = 0; n < Hn; n++) acc[n] = fmaf(a, br[n], acc[n]);
    }
    #pragma unroll
    for (int n = 0; n < Hn; n++) {
        #pragma unroll
        for (int o = 16; o; o >>= 1) acc[n] += __shfl_xor_sync(0xffffffffu, acc[n], o);
    }
    if (lane == 0) {
        #pragma unroll
        for (int n = 0; n < Hn; n++)
            beta[warp * Hn + n] = 1.f / (1.f + expf(-acc[n]));
    }
}

// ---------------- cp.async helpers (recurrence) ----------------
__device__ __forceinline__ void cp16(uint32_t dst, const void* src) {
    asm volatile("cp.async.ca.shared.global [%0], [%1], 16;" :: "r"(dst), "l"(src));
}
__device__ __forceinline__ void cp4(uint32_t dst, const void* src) {
    asm volatile("cp.async.ca.shared.global [%0], [%1], 4;" :: "r"(dst), "l"(src));
}

// ---------------- gated delta-rule recurrence (v5: barrier-free, 4-deep pipe) ---
__global__ __launch_bounds__(128) void recurrence(
    const float* __restrict__ q, const float* __restrict__ k, const float* __restrict__ v,
    const float* __restrict__ g, const float* __restrict__ beta, float* __restrict__ o)
{
    const int bh = blockIdx.x;
    const int b = bh >> 4, h = bh & 15;
    const int jbase = (blockIdx.y << 5);
    const int tid = threadIdx.x;
    const int w    = tid >> 5;
    const int lane = tid & 31;
    const int r4   = lane >> 3;
    const int c    = lane & 7;

    __shared__ __align__(16) float sw[4][4][400];   // [warp][buf][data]

    unsigned long long S2[16];
    #pragma unroll
    for (int i = 0; i < 16; i++) S2[i] = 0ull;

    const size_t rs = (size_t)CHn;
    const size_t base0 = ((size_t)b * Tn) * rs + (size_t)h * DKn;
    const int jcol = jbase + w * 8;
    const size_t bbase = (size_t)(b * Tn) * Hn + h;

    float* swarp = &sw[w][0][0];
    const uint32_t sb32 = (uint32_t)__cvta_generic_to_shared(swarp);

    auto issue_copy = [&](int t, int bb) {
        const uint32_t d = sb32 + (uint32_t)bb * 400u * 4u;
        const size_t row = base0 + (size_t)t * rs;
        cp16(d +            lane * 16, k + row + lane * 4);
        cp16(d + 128 * 4 +  lane * 16, g + row + lane * 4);
        cp16(d + 256 * 4 +  lane * 16, q + row + lane * 4);
        if (lane < 2)  cp16(d + 384 * 4 + lane * 16, v + row + jcol + lane * 4);
        if (lane == 2) cp4 (d + 392 * 4, beta + bbase + (size_t)t * Hn);
    };

    issue_copy(0, 0);
    asm volatile("cp.async.commit_group;");
    issue_copy(1, 1);
    asm volatile("cp.async.commit_group;");
    issue_copy(2, 2);
    asm volatile("cp.async.commit_group;");

    size_t obase = base0 + jcol + c;

    #pragma unroll 1
    for (int t = 0; t < Tn; t++) {
        const int bb = t & 3;
        if (t + 3 < Tn) issue_copy(t + 3, (t + 3) & 3);
        asm volatile("cp.async.commit_group;");
        asm volatile("cp.async.wait_group 3;");
        __syncwarp();

        const float* buf = &sw[w][bb][0];
        const ulonglong2* kp = (const ulonglong2*)(buf +       r4 * 32);
        const ulonglong2* gp = (const ulonglong2*)(buf + 128 + r4 * 32);
        const ulonglong2* qp = (const ulonglong2*)(buf + 256 + r4 * 32);

        unsigned long long k2[16];
        unsigned long long p[4] = {0ull, 0ull, 0ull, 0ull};
        #pragma unroll
        for (int i = 0; i < 8; i++) {
            ulonglong2 kv = kp[i];
            ulonglong2 gv = gp[i];
            k2[2*i]   = kv.x;
            k2[2*i+1] = kv.y;
            asm("mul.rn.f32x2 %0, %0, %1;" : "+l"(S2[2*i])   : "l"(gv.x));
            asm("mul.rn.f32x2 %0, %0, %1;" : "+l"(S2[2*i+1]) : "l"(gv.y));
        }
        #pragma unroll
        for (int i = 0; i < 16; i++)
            asm("fma.rn.f32x2 %0, %1, %2, %0;" : "+l"(p[i & 3]) : "l"(k2[i]), "l"(S2[i]));

        float partial;
        {
            unsigned long long p01, p23, pt;
            asm("add.rn.f32x2 %0, %1, %2;" : "=l"(p01) : "l"(p[0]), "l"(p[1]));
            asm("add.rn.f32x2 %0, %1, %2;" : "=l"(p23) : "l"(p[2]), "l"(p[3]));
            asm("add.rn.f32x2 %0, %1, %2;" : "=l"(pt)  : "l"(p01),  "l"(p23));
            unsigned int lo, hi;
            asm("mov.b64 {%0,%1}, %2;" : "=r"(lo), "=r"(hi) : "l"(pt));
            partial = __uint_as_float(lo) + __uint_as_float(hi);
        }
        partial += __shfl_xor_sync(0xffffffffu, partial, 8);
        partial += __shfl_xor_sync(0xffffffffu, partial, 16);

        const float vv = buf[384 + c];
        const float bt_ = buf[392];
        const float delta = (vv - partial) * bt_;
        unsigned long long d2;
        asm("mov.b64 %0, {%1,%1};" : "=l"(d2) : "r"(__float_as_uint(delta)));

        unsigned long long oacc[4] = {0ull, 0ull, 0ull, 0ull};
        #pragma unroll
        for (int i = 0; i < 8; i++) {
            ulonglong2 qv = qp[i];
            asm("fma.rn.f32x2 %0, %1, %2, %0;" : "+l"(S2[2*i])   : "l"(k2[2*i]),   "l"(d2));
            asm("fma.rn.f32x2 %0, %1, %2, %0;" : "+l"(S2[2*i+1]) : "l"(k2[2*i+1]), "l"(d2));
            asm("fma.rn.f32x2 %0, %1, %2, %0;" : "+l"(oacc[(2*i) & 3])   : "l"(qv.x), "l"(S2[2*i]));
            asm("fma.rn.f32x2 %0, %1, %2, %0;" : "+l"(oacc[(2*i+1) & 3]) : "l"(qv.y), "l"(S2[2*i+1]));
        }
        float oo;
        {
            unsigned long long o01, o23, ot;
            asm("add.rn.f32x2 %0, %1, %2;" : "=l"(o01) : "l"(oacc[0]), "l"(oacc[1]));
            asm("add.rn.f32x2 %0, %1, %2;" : "=l"(o23) : "l"(oacc[2]), "l"(oacc[3]));
            asm("add.rn.f32x2 %0, %1, %2;" : "=l"(ot)  : "l"(o01),     "l"(o23));
            unsigned int lo, hi;
            asm("mov.b64 {%0,%1}, %2;" : "=r"(lo), "=r"(hi) : "l"(ot));
            oo = __uint_as_float(lo) + __uint_as_float(hi);
        }
        oo += __shfl_xor_sync(0xffffffffu, oo, 8);
        oo += __shfl_xor_sync(0xffffffffu, oo, 16);

        if (r4 == 0) o[obase] = oo;
        obase += rs;
    }
}

// ---------------- gated RMSNorm -> fp16 output ----------------
__global__ __launch_bounds__(256) void rms_gate_h(
    const float* __restrict__ o, const float* __restrict__ g2,
    const float* __restrict__ nw, __half* __restrict__ oh)
{
    int warp = (blockIdx.x * blockDim.x + threadIdx.x) >> 5;
    int lane = threadIdx.x & 31;
    if (warp >= BTn * Hn) return;

    const float4* op = (const float4*)(o + (size_t)warp * DVn);
    const float4* gp = (const float4*)(g2 + (size_t)warp * DVn);
    const float4* wp = (const float4*)nw;

    float4 v = op[lane];
    float ss = v.x*v.x + v.y*v.y + v.z*v.z + v.w*v.w;
    #pragma unroll
    for (int off = 16; off; off >>= 1) ss += __shfl_xor_sync(0xffffffffu, ss, off);
    float r = rsqrtf(ss * (1.f / 128.f) + 1e-6f);

    float4 w = wp[lane];
    float4 gg = gp[lane];
    float ox = v.x * r * w.x * (1.f / (1.f + expf(-gg.x)));
    float oy = v.y * r * w.y * (1.f / (1.f + expf(-gg.y)));
    float oz = v.z * r * w.z * (1.f / (1.f + expf(-gg.z)));
    float ow = v.w * r * w.w * (1.f / (1.f + expf(-gg.w)));
    uint2 pk;
    pk.x = packh2(ox, oy);
    pk.y = packh2(oz, ow);
    *(uint2*)(oh + (size_t)warp * DVn + lane * 4) = pk;
}

// ---------------- launcher ----------------
extern "C" void kernel_launch(void* const* d_in, const int* in_sizes, int n_in,
                              void* d_out, int out_size)
{
    const float* x     = (const float*)d_in[0];
    const float* Wq    = (const float*)d_in[1];
    const float* Wk    = (const float*)d_in[2];
    const float* Wv    = (const float*)d_in[3];
    const float* convq = (const float*)d_in[4];
    const float* convk = (const float*)d_in[5];
    const float* convv = (const float*)d_in[6];
    const float* A_log = (const float*)d_in[7];
    const float* Wfa   = (const float*)d_in[8];
    const float* Wfb   = (const float*)d_in[9];
    const float* dtb   = (const float*)d_in[10];
    const float* Wb    = (const float*)d_in[11];
    const float* Wga   = (const float*)d_in[12];
    const float* Wgb   = (const float*)d_in[13];
    const float* nw    = (const float*)d_in[14];
    const float* Wo    = (const float*)d_in[15];

    float *xq, *xk, *xv, *q, *k, *v, *gd, *g2b, *ob, *p1, *p2, *bt;
    __half *xh, *wqh, *wkh, *wvh, *woh, *wfah, *wgah, *wfbh, *wgbh, *t1h, *t2h, *oh;
    cudaGetSymbolAddress((void**)&xq,  g_xq);
    cudaGetSymbolAddress((void**)&xk,  g_xk);
    cudaGetSymbolAddress((void**)&xv,  g_xv);
    cudaGetSymbolAddress((void**)&q,   g_q);
    cudaGetSymbolAddress((void**)&k,   g_k);
    cudaGetSymbolAddress((void**)&v,   g_v);
    cudaGetSymbolAddress((void**)&gd,  g_gd);
    cudaGetSymbolAddress((void**)&g2b, g_g2);
    cudaGetSymbolAddress((void**)&ob,  g_o);
    cudaGetSymbolAddress((void**)&p1,  g_p1);
    cudaGetSymbolAddress((void**)&p2,  g_p2);
    cudaGetSymbolAddress((void**)&bt,  g_bt);
    cudaGetSymbolAddress((void**)&xh,   g_xh);
    cudaGetSymbolAddress((void**)&wqh,  g_wqh);
    cudaGetSymbolAddress((void**)&wkh,  g_wkh);
    cudaGetSymbolAddress((void**)&wvh,  g_wvh);
    cudaGetSymbolAddress((void**)&woh,  g_woh);
    cudaGetSymbolAddress((void**)&wfah, g_wfah);
    cudaGetSymbolAddress((void**)&wgah, g_wgah);
    cudaGetSymbolAddress((void**)&wfbh, g_wfbh);
    cudaGetSymbolAddress((void**)&wgbh, g_wgbh);
    cudaGetSymbolAddress((void**)&t1h,  g_t1h);
    cudaGetSymbolAddress((void**)&t2h,  g_t2h);
    cudaGetSymbolAddress((void**)&oh,   g_oh);

    dim3 gBig(CHn / 128, BTn / 128);          // (16, 32)
    dim3 gNarrowSK(1, BTn / 128, 4);          // (1, 32, 4)
    int  tot = BTn * CHn;
    int  eb  = (tot + 255) / 256;
    int  nsm = BTn * DVn;

    auto cvtGrid = [](int n) { return (n / 8 + 255) / 256; };
    const int nBig = HIDn * CHn;
    const int nNar = HIDn * DVn;

    // idx 0-2: conversions needed by the first big GEMM
    f32_to_f16<<<cvtGrid(BTn * HIDn), 256>>>(x, xh, BTn * HIDn);
    f32_to_f16<<<cvtGrid(nBig), 256>>>(Wq, wqh, nBig);
    f32_to_f16<<<cvtGrid(nBig), 256>>>(Wk, wkh, nBig);

    // idx 3: first big projection  <-- ncu capture target (launch index 3)
    hgemm<<<gBig, 128>>>(BTn, CHn, HIDn, xh, wqh, xq);

    // idx 4: Wv conversion, idx 5-6: remaining big projections
    f32_to_f16<<<cvtGrid(nBig), 256>>>(Wv, wvh, nBig);
    hgemm<<<gBig, 128>>>(BTn, CHn, HIDn, xh, wkh, xk);
    hgemm<<<gBig, 128>>>(BTn, CHn, HIDn, xh, wvh, xv);

    // idx 7-11: remaining weight conversions
    f32_to_f16<<<cvtGrid(nBig), 256>>>(Wo, woh, nBig);
    f32_to_f16<<<cvtGrid(nNar), 256>>>(Wfa, wfah, nNar);
    f32_to_f16<<<cvtGrid(nNar), 256>>>(Wga, wgah, nNar);
    f32_to_f16<<<cvtGrid(nNar), 256>>>(Wfb, wfbh, nNar);
    f32_to_f16<<<cvtGrid(nNar), 256>>>(Wgb, wgbh, nNar);

    // idx 12: beta
    beta_proj<<<(BTn * 32 + 255) / 256, 256>>>(x, Wb, bt);

    // idx 13-14: narrow split-K GEMMs
    hgemm_splitk4<<<gNarrowSK, 128>>>(BTn, DVn, HIDn, xh, wfah, p1);
    hgemm_splitk4<<<gNarrowSK, 128>>>(BTn, DVn, HIDn, xh, wgah, p2);

    // idx 15-16: split-K reductions -> fp16
    reduce4h<<<(nsm / 4 + 255) / 256, 256>>>(p1, t1h, nsm);
    reduce4h<<<(nsm / 4 + 255) / 256, 256>>>(p2, t2h, nsm);

    // idx 17: conv+silu for v (elementwise)
    conv_silu_v<<<eb, 256>>>(xv, convv, v);

    // idx 18: fused conv+silu+l2norm for q,k
    conv_silu_l2<<<dim3((BTn * Hn) / 8, 2), 256>>>(xq, xk, convq, convk, q, k);

    // idx 19: decay gate GEMM with fused softplus/exp epilogue
    hgemm_gate<<<gBig, 128>>>(BTn, CHn, DVn, t1h, wfbh, gd, dtb, A_log);

    // idx 20: output gate GEMM
    hgemm<<<gBig, 128>>>(BTn, CHn, DVn, t2h, wgbh, g2b);

    // idx 21: recurrence (v5)
    recurrence<<<dim3(Bn * Hn, 4), 128>>>(q, k, v, gd, bt, ob);

    // idx 22: gated RMSNorm -> fp16
    rms_gate_h<<<(BTn * Hn) / 8, 256>>>(ob, g2b, nw, oh);

    // idx 23: output projection
    hgemm<<<gBig, 128>>>(BTn, CHn, CHn, oh, woh, (float*)d_out);
}